// round 12
// baseline (speedup 1.0000x reference)
#include <cuda_runtime.h>
#include <cuda_bf16.h>
#include <cstdint>

#define D 128
#define BM 64
#define NT 256

// smem layout (bytes): A hi 16K | A lo 16K | B hi 32K | B lo 32K
#define OFF_AHI 0
#define OFF_ALO 16384
#define OFF_BHI 32768
#define OFF_BLO 65536
#define FUSE_SMEM 98304

// ---- helpers ----
__device__ __forceinline__ void split2(float a, float b, unsigned& hi, unsigned& lo) {
    __nv_bfloat16 ha = __float2bfloat16_rn(a);
    __nv_bfloat16 hb = __float2bfloat16_rn(b);
    float ra = a - __bfloat162float(ha);
    float rb = b - __bfloat162float(hb);
    __nv_bfloat162 hv; hv.x = ha; hv.y = hb;
    __nv_bfloat162 lv = __floats2bfloat162_rn(ra, rb);
    hi = *reinterpret_cast<unsigned*>(&hv);
    lo = *reinterpret_cast<unsigned*>(&lv);
}

__device__ __forceinline__ unsigned smem_u32(const void* p) {
    unsigned a;
    asm("{ .reg .u64 t; cvta.to.shared.u64 t, %1; cvt.u32.u64 %0, t; }"
        : "=r"(a) : "l"(p));
    return a;
}

#define STS64(addr, v0, v1)                                                  \
    asm volatile("st.shared.v2.b32 [%0], {%1,%2};" ::"r"(addr), "r"(v0),     \
                 "r"(v1) : "memory")

#define STS128V(addr, v0, v1, v2, v3)                                        \
    asm volatile("st.shared.v4.b32 [%0], {%1,%2,%3,%4};" ::"r"(addr),        \
                 "r"(v0), "r"(v1), "r"(v2), "r"(v3) : "memory")

#define LDSM4(r0, r1, r2, r3, addr)                                          \
    asm volatile("ldmatrix.sync.aligned.m8n8.x4.shared.b16 "                 \
                 "{%0,%1,%2,%3}, [%4];"                                      \
                 : "=r"(r0), "=r"(r1), "=r"(r2), "=r"(r3) : "r"(addr))

#define MMA16816(d, a, b0, b1)                                               \
    asm volatile("mma.sync.aligned.m16n8k16.row.col.f32.bf16.bf16.f32 "      \
                 "{%0,%1,%2,%3}, {%4,%5,%6,%7}, {%8,%9}, {%0,%1,%2,%3};"     \
                 : "+f"((d)[0]), "+f"((d)[1]), "+f"((d)[2]), "+f"((d)[3])    \
                 : "r"((a)[0]), "r"((a)[1]), "r"((a)[2]), "r"((a)[3]),       \
                   "r"(b0), "r"(b1))

#define STG_CS_64(ptr, a, b)                                                 \
    asm volatile("st.global.cs.v2.f32 [%0], {%1,%2};" ::"l"(ptr), "f"(a),    \
                 "f"(b) : "memory")

// swizzled byte offset inside a 256B-pitch bf16 tile (chunk = 16B unit)
__device__ __forceinline__ unsigned sw_off(int row, int chunk) {
    return (unsigned)(row * 256 + ((chunk ^ (row & 7)) << 4));
}

// ============================================================================
// Fused GINConv: per block of 64 destination rows, 256 threads (8 warps).
//  Phase 0: W (L1-hot) -> smem B hi/lo [n][k] bf16, conflict-free STS128.
//  Phase 1: gather 8 rows/warp (int4-vectorized colidx), split-bf16 -> smem A.
//  Phase 2: HMMA, warp tile 32x32: D = Ahi*Bhi + Ahi*Blo + Alo*Bhi.
// ============================================================================
__global__ void __launch_bounds__(NT, 2)
ginconv_fused(const float4* __restrict__ X4,
              const float* __restrict__ W,
              const int* __restrict__ rowptr,
              const int* __restrict__ colidx,
              float* __restrict__ out,
              int n) {
    extern __shared__ char smem[];
    const unsigned sb = smem_u32(smem);
    const int tid  = threadIdx.x;
    const int wid  = tid >> 5;
    const int lane = tid & 31;
    const int row0 = blockIdx.x * BM;

    // ---- Phase 0: W -> smem B tiles (hi/lo), [n][k] bf16, swizzled ----
    // thread t: nrow = t & 127 (lanes -> consecutive rows, coalesced LDG);
    // chunk group g = t>>7 (0..1), chunks g*8 .. g*8+7 (chunk = 8 k-values).
    {
        const int nrow = tid & 127;
        const int g    = tid >> 7;
#pragma unroll
        for (int c8 = 0; c8 < 8; c8++) {
            const int c = g * 8 + c8;  // 16B chunk index 0..15
            unsigned hi[4], lo[4];
#pragma unroll
            for (int p = 0; p < 4; p++) {
                const int k = c * 8 + p * 2;
                const float wa = W[(size_t)k * D + nrow];
                const float wb = W[(size_t)(k + 1) * D + nrow];
                split2(wa, wb, hi[p], lo[p]);
            }
            const unsigned so = sw_off(nrow, c);
            STS128V(sb + OFF_BHI + so, hi[0], hi[1], hi[2], hi[3]);
            STS128V(sb + OFF_BLO + so, lo[0], lo[1], lo[2], lo[3]);
        }
    }

    // ---- Phase 1: gather 8 rows per warp into smem A tiles ----
#pragma unroll 1
    for (int t = 0; t < 8; t++) {
        const int lr = wid * 8 + t;
        const int r  = row0 + lr;
        float4 acc = make_float4(0.f, 0.f, 0.f, 0.f);
        if (r < n) {
            int e        = rowptr[r];
            const int e1 = rowptr[r + 1];
            // scalar prologue to 16B-align colidx
            while (e < e1 && (e & 3)) {
                float4 v = X4[(size_t)colidx[e] * 32 + lane];
                acc.x += v.x; acc.y += v.y; acc.z += v.z; acc.w += v.w;
                e++;
            }
            // 8-edge main loop: 2 broadcast int4 colidx loads + 8 gathers
            for (; e + 8 <= e1; e += 8) {
                const int4 ca = *reinterpret_cast<const int4*>(&colidx[e]);
                const int4 cb = *reinterpret_cast<const int4*>(&colidx[e + 4]);
                float4 v[8];
                v[0] = X4[(size_t)ca.x * 32 + lane];
                v[1] = X4[(size_t)ca.y * 32 + lane];
                v[2] = X4[(size_t)ca.z * 32 + lane];
                v[3] = X4[(size_t)ca.w * 32 + lane];
                v[4] = X4[(size_t)cb.x * 32 + lane];
                v[5] = X4[(size_t)cb.y * 32 + lane];
                v[6] = X4[(size_t)cb.z * 32 + lane];
                v[7] = X4[(size_t)cb.w * 32 + lane];
#pragma unroll
                for (int i = 0; i < 8; i++) {
                    acc.x += v[i].x; acc.y += v[i].y;
                    acc.z += v[i].z; acc.w += v[i].w;
                }
            }
            for (; e < e1; e++) {
                float4 v = X4[(size_t)colidx[e] * 32 + lane];
                acc.x += v.x; acc.y += v.y; acc.z += v.z; acc.w += v.w;
            }
        }
        unsigned h0, l0, h1, l1;
        split2(acc.x, acc.y, h0, l0);
        split2(acc.z, acc.w, h1, l1);
        // lane owns features 4*lane..4*lane+3 -> 8B at chunk lane>>1
        const unsigned so = (unsigned)(lr * 256) +
                            ((unsigned)(((lane >> 1) ^ (lr & 7)) << 4)) +
                            (unsigned)((lane & 1) * 8);
        STS64(sb + OFF_AHI + so, h0, h1);
        STS64(sb + OFF_ALO + so, l0, l1);
    }
    __syncthreads();

    // ---- Phase 2: HMMA. 8 warps, warp tile 32 rows x 32 cols ----
    const int wm = wid >> 2;  // 0..1 : rows wm*32 .. +31
    const int wn = wid & 3;   // 0..3 : cols wn*32 .. +31

    float acc[2][4][4];
#pragma unroll
    for (int mt = 0; mt < 2; mt++)
#pragma unroll
        for (int nt = 0; nt < 4; nt++)
#pragma unroll
            for (int i = 0; i < 4; i++) acc[mt][nt][i] = 0.f;

    const int lrow = lane & 15;
    const int lch  = lane >> 4;

#pragma unroll 2
    for (int ks = 0; ks < 8; ks++) {
        const int cb = ks * 2 + lch;

        unsigned ah[2][4], al[2][4];
#pragma unroll
        for (int mt = 0; mt < 2; mt++) {
            const unsigned so = sw_off(wm * 32 + mt * 16 + lrow, cb);
            LDSM4(ah[mt][0], ah[mt][1], ah[mt][2], ah[mt][3], sb + OFF_AHI + so);
            LDSM4(al[mt][0], al[mt][1], al[mt][2], al[mt][3], sb + OFF_ALO + so);
        }
        unsigned bh[2][4], bl[2][4];
#pragma unroll
        for (int np = 0; np < 2; np++) {
            const unsigned so = sw_off(wn * 32 + np * 16 + lrow, cb);
            LDSM4(bh[np][0], bh[np][1], bh[np][2], bh[np][3], sb + OFF_BHI + so);
            LDSM4(bl[np][0], bl[np][1], bl[np][2], bl[np][3], sb + OFF_BLO + so);
        }

#pragma unroll
        for (int mt = 0; mt < 2; mt++)
#pragma unroll
            for (int nt = 0; nt < 4; nt++) {
                const int np = nt >> 1, hf = nt & 1;
                MMA16816(acc[mt][nt], ah[mt], bh[np][hf], bh[np][hf + 2]);
                MMA16816(acc[mt][nt], ah[mt], bl[np][hf], bl[np][hf + 2]);
                MMA16816(acc[mt][nt], al[mt], bh[np][hf], bh[np][hf + 2]);
            }
    }

    // ---- Epilogue ----
#pragma unroll
    for (int mt = 0; mt < 2; mt++) {
        const int rg = row0 + wm * 32 + mt * 16 + (lane >> 2);
#pragma unroll
        for (int nt = 0; nt < 4; nt++) {
            const int col = wn * 32 + nt * 8 + (lane & 3) * 2;
            if (rg < n)
                STG_CS_64(&out[(size_t)rg * D + col], acc[mt][nt][0],
                          acc[mt][nt][1]);
            if (rg + 8 < n)
                STG_CS_64(&out[(size_t)(rg + 8) * D + col], acc[mt][nt][2],
                          acc[mt][nt][3]);
        }
    }
}

extern "C" void kernel_launch(void* const* d_in, const int* in_sizes, int n_in,
                              void* d_out, int out_size) {
    const float* X      = (const float*)d_in[0];
    const float* W      = (const float*)d_in[1];
    const int*   rowptr = (const int*)d_in[2];
    const int*   colidx = (const int*)d_in[3];
    float*       out    = (float*)d_out;

    const int n = in_sizes[2] - 1;  // row_pointers has N+1 entries

    cudaFuncSetAttribute(ginconv_fused,
                         cudaFuncAttributeMaxDynamicSharedMemorySize,
                         FUSE_SMEM);

    const int grid = (n + BM - 1) / BM;
    ginconv_fused<<<grid, NT, FUSE_SMEM>>>((const float4*)X, W, rowptr, colidx,
                                           out, n);
}

// round 13
// speedup vs baseline: 1.3761x; 1.3761x over previous
#include <cuda_runtime.h>
#include <cuda_bf16.h>
#include <cstdint>

#define D 128
#define BM 64
#define NT 512

// smem layout (bytes): A hi 16K | A lo 16K | B hi 32K | B lo 32K
#define OFF_AHI 0
#define OFF_ALO 16384
#define OFF_BHI 32768
#define OFF_BLO 65536
#define FUSE_SMEM 98304

// ---- helpers ----
__device__ __forceinline__ void split2(float a, float b, unsigned& hi, unsigned& lo) {
    __nv_bfloat16 ha = __float2bfloat16_rn(a);
    __nv_bfloat16 hb = __float2bfloat16_rn(b);
    float ra = a - __bfloat162float(ha);
    float rb = b - __bfloat162float(hb);
    __nv_bfloat162 hv; hv.x = ha; hv.y = hb;
    __nv_bfloat162 lv = __floats2bfloat162_rn(ra, rb);
    hi = *reinterpret_cast<unsigned*>(&hv);
    lo = *reinterpret_cast<unsigned*>(&lv);
}

__device__ __forceinline__ unsigned smem_u32(const void* p) {
    unsigned a;
    asm("{ .reg .u64 t; cvta.to.shared.u64 t, %1; cvt.u32.u64 %0, t; }"
        : "=r"(a) : "l"(p));
    return a;
}

#define STS64(addr, v0, v1)                                                  \
    asm volatile("st.shared.v2.b32 [%0], {%1,%2};" ::"r"(addr), "r"(v0),     \
                 "r"(v1) : "memory")

#define STS128V(addr, v0, v1, v2, v3)                                        \
    asm volatile("st.shared.v4.b32 [%0], {%1,%2,%3,%4};" ::"r"(addr),        \
                 "r"(v0), "r"(v1), "r"(v2), "r"(v3) : "memory")

#define LDSM4(r0, r1, r2, r3, addr)                                          \
    asm volatile("ldmatrix.sync.aligned.m8n8.x4.shared.b16 "                 \
                 "{%0,%1,%2,%3}, [%4];"                                      \
                 : "=r"(r0), "=r"(r1), "=r"(r2), "=r"(r3) : "r"(addr))

#define MMA16816(d, a, b0, b1)                                               \
    asm volatile("mma.sync.aligned.m16n8k16.row.col.f32.bf16.bf16.f32 "      \
                 "{%0,%1,%2,%3}, {%4,%5,%6,%7}, {%8,%9}, {%0,%1,%2,%3};"     \
                 : "+f"((d)[0]), "+f"((d)[1]), "+f"((d)[2]), "+f"((d)[3])    \
                 : "r"((a)[0]), "r"((a)[1]), "r"((a)[2]), "r"((a)[3]),       \
                   "r"(b0), "r"(b1))

#define STG_CS_64(ptr, a, b)                                                 \
    asm volatile("st.global.cs.v2.f32 [%0], {%1,%2};" ::"l"(ptr), "f"(a),    \
                 "f"(b) : "memory")

// swizzled byte offset inside a 256B-pitch bf16 tile (chunk = 16B unit)
__device__ __forceinline__ unsigned sw_off(int row, int chunk) {
    return (unsigned)(row * 256 + ((chunk ^ (row & 7)) << 4));
}

// ============================================================================
// Fused GINConv: per block of 64 destination rows, 512 threads (16 warps).
//  Phase 0: W (L1-hot) -> smem B hi/lo [n][k] bf16, conflict-free STS128.
//  Phase 1: gather 4 rows/warp (int4-vectorized colidx), split-bf16 -> smem A.
//  Phase 2: HMMA, warp tile 16x32: D = Ahi*Bhi + Ahi*Blo + Alo*Bhi.
// (R11 config; only change vs R11 is the int4 colidx vectorization.)
// ============================================================================
__global__ void __launch_bounds__(NT, 2)
ginconv_fused(const float4* __restrict__ X4,
              const float* __restrict__ W,
              const int* __restrict__ rowptr,
              const int* __restrict__ colidx,
              float* __restrict__ out,
              int n) {
    extern __shared__ char smem[];
    const unsigned sb = smem_u32(smem);
    const int tid  = threadIdx.x;
    const int wid  = tid >> 5;
    const int lane = tid & 31;
    const int row0 = blockIdx.x * BM;

    // ---- Phase 0: W -> smem B tiles (hi/lo), [n][k] bf16, swizzled ----
    // thread t: nrow = t & 127 (lanes -> consecutive rows, coalesced LDG);
    // chunk group g = t>>7 (0..3), chunks g*4 .. g*4+3 (chunk = 8 k-values).
    {
        const int nrow = tid & 127;
        const int g    = tid >> 7;  // 0..3
#pragma unroll
        for (int c8 = 0; c8 < 4; c8++) {
            const int c = g * 4 + c8;  // 16B chunk index 0..15
            unsigned hi[4], lo[4];
#pragma unroll
            for (int p = 0; p < 4; p++) {
                const int k = c * 8 + p * 2;
                const float wa = W[(size_t)k * D + nrow];
                const float wb = W[(size_t)(k + 1) * D + nrow];
                split2(wa, wb, hi[p], lo[p]);
            }
            const unsigned so = sw_off(nrow, c);
            STS128V(sb + OFF_BHI + so, hi[0], hi[1], hi[2], hi[3]);
            STS128V(sb + OFF_BLO + so, lo[0], lo[1], lo[2], lo[3]);
        }
    }

    // ---- Phase 1: gather 4 rows per warp into smem A tiles ----
#pragma unroll 1
    for (int t = 0; t < 4; t++) {
        const int lr = wid * 4 + t;
        const int r  = row0 + lr;
        float4 acc = make_float4(0.f, 0.f, 0.f, 0.f);
        if (r < n) {
            int e        = rowptr[r];
            const int e1 = rowptr[r + 1];
            // scalar prologue to 16B-align colidx
            while (e < e1 && (e & 3)) {
                float4 v = X4[(size_t)colidx[e] * 32 + lane];
                acc.x += v.x; acc.y += v.y; acc.z += v.z; acc.w += v.w;
                e++;
            }
            // 8-edge main loop: 2 broadcast int4 colidx loads + 8 gathers
            for (; e + 8 <= e1; e += 8) {
                const int4 ca = *reinterpret_cast<const int4*>(&colidx[e]);
                const int4 cb = *reinterpret_cast<const int4*>(&colidx[e + 4]);
                float4 v[8];
                v[0] = X4[(size_t)ca.x * 32 + lane];
                v[1] = X4[(size_t)ca.y * 32 + lane];
                v[2] = X4[(size_t)ca.z * 32 + lane];
                v[3] = X4[(size_t)ca.w * 32 + lane];
                v[4] = X4[(size_t)cb.x * 32 + lane];
                v[5] = X4[(size_t)cb.y * 32 + lane];
                v[6] = X4[(size_t)cb.z * 32 + lane];
                v[7] = X4[(size_t)cb.w * 32 + lane];
#pragma unroll
                for (int i = 0; i < 8; i++) {
                    acc.x += v[i].x; acc.y += v[i].y;
                    acc.z += v[i].z; acc.w += v[i].w;
                }
            }
            for (; e < e1; e++) {
                float4 v = X4[(size_t)colidx[e] * 32 + lane];
                acc.x += v.x; acc.y += v.y; acc.z += v.z; acc.w += v.w;
            }
        }
        unsigned h0, l0, h1, l1;
        split2(acc.x, acc.y, h0, l0);
        split2(acc.z, acc.w, h1, l1);
        // lane owns features 4*lane..4*lane+3 -> 8B at chunk lane>>1
        const unsigned so = (unsigned)(lr * 256) +
                            ((unsigned)(((lane >> 1) ^ (lr & 7)) << 4)) +
                            (unsigned)((lane & 1) * 8);
        STS64(sb + OFF_AHI + so, h0, h1);
        STS64(sb + OFF_ALO + so, l0, l1);
    }
    __syncthreads();

    // ---- Phase 2: HMMA. 16 warps, warp tile 16 rows x 32 cols ----
    const int wm = wid >> 2;  // 0..3 : rows wm*16 .. +15
    const int wn = wid & 3;   // 0..3 : cols wn*32 .. +31

    float acc[4][4];
#pragma unroll
    for (int nt = 0; nt < 4; nt++)
#pragma unroll
        for (int i = 0; i < 4; i++) acc[nt][i] = 0.f;

    const int lrow = lane & 15;
    const int lch  = lane >> 4;

#pragma unroll 2
    for (int ks = 0; ks < 8; ks++) {
        const int cb = ks * 2 + lch;

        unsigned ah[4], al[4];
        {
            const unsigned so = sw_off(wm * 16 + lrow, cb);
            LDSM4(ah[0], ah[1], ah[2], ah[3], sb + OFF_AHI + so);
            LDSM4(al[0], al[1], al[2], al[3], sb + OFF_ALO + so);
        }
#pragma unroll
        for (int np = 0; np < 2; np++) {
            unsigned bh[4], bl[4];
            const unsigned so = sw_off(wn * 32 + np * 16 + lrow, cb);
            LDSM4(bh[0], bh[1], bh[2], bh[3], sb + OFF_BHI + so);
            LDSM4(bl[0], bl[1], bl[2], bl[3], sb + OFF_BLO + so);
#pragma unroll
            for (int hf = 0; hf < 2; hf++) {
                const int nt = np * 2 + hf;
                MMA16816(acc[nt], ah, bh[hf], bh[hf + 2]);
                MMA16816(acc[nt], ah, bl[hf], bl[hf + 2]);
                MMA16816(acc[nt], al, bh[hf], bh[hf + 2]);
            }
        }
    }

    // ---- Epilogue ----
    {
        const int rg = row0 + wm * 16 + (lane >> 2);
#pragma unroll
        for (int nt = 0; nt < 4; nt++) {
            const int col = wn * 32 + nt * 8 + (lane & 3) * 2;
            if (rg < n)
                STG_CS_64(&out[(size_t)rg * D + col], acc[nt][0], acc[nt][1]);
            if (rg + 8 < n)
                STG_CS_64(&out[(size_t)(rg + 8) * D + col], acc[nt][2],
                          acc[nt][3]);
        }
    }
}

extern "C" void kernel_launch(void* const* d_in, const int* in_sizes, int n_in,
                              void* d_out, int out_size) {
    const float* X      = (const float*)d_in[0];
    const float* W      = (const float*)d_in[1];
    const int*   rowptr = (const int*)d_in[2];
    const int*   colidx = (const int*)d_in[3];
    float*       out    = (float*)d_out;

    const int n = in_sizes[2] - 1;  // row_pointers has N+1 entries

    cudaFuncSetAttribute(ginconv_fused,
                         cudaFuncAttributeMaxDynamicSharedMemorySize,
                         FUSE_SMEM);

    const int grid = (n + BM - 1) / BM;
    ginconv_fused<<<grid, NT, FUSE_SMEM>>>((const float4*)X, W, rowptr, colidx,
                                           out, n);
}

// round 15
// speedup vs baseline: 1.4648x; 1.0645x over previous
#include <cuda_runtime.h>
#include <cuda_bf16.h>
#include <cstdint>

#define D 128
#define BM 64
#define NT 512

// smem layout (bytes): A hi 16K | A lo 16K | B hi 32K | B lo 32K
#define OFF_AHI 0
#define OFF_ALO 16384
#define OFF_BHI 32768
#define OFF_BLO 65536
#define FUSE_SMEM 98304

// Pre-swizzled B tile images (bf16 hi/lo, [n][k] layout, 32KB each!)
__device__ uint4 g_BHi4[2048];
__device__ uint4 g_BLo4[2048];

typedef unsigned long long ull_t;

// ---- helpers ----
__device__ __forceinline__ void split2(float a, float b, unsigned& hi, unsigned& lo) {
    __nv_bfloat16 ha = __float2bfloat16_rn(a);
    __nv_bfloat16 hb = __float2bfloat16_rn(b);
    float ra = a - __bfloat162float(ha);
    float rb = b - __bfloat162float(hb);
    __nv_bfloat162 hv; hv.x = ha; hv.y = hb;
    __nv_bfloat162 lv = __floats2bfloat162_rn(ra, rb);
    hi = *reinterpret_cast<unsigned*>(&hv);
    lo = *reinterpret_cast<unsigned*>(&lv);
}

__device__ __forceinline__ void unpack2(ull_t v, float& lo, float& hi) {
    asm("mov.b64 {%0,%1}, %2;" : "=f"(lo), "=f"(hi) : "l"(v));
}

#define ADD2(d, s)                                                           \
    asm("add.rn.f32x2 %0, %0, %1;" : "+l"(d) : "l"(s))

__device__ __forceinline__ unsigned smem_u32(const void* p) {
    unsigned a;
    asm("{ .reg .u64 t; cvta.to.shared.u64 t, %1; cvt.u32.u64 %0, t; }"
        : "=r"(a) : "l"(p));
    return a;
}

#define STS64(addr, v0, v1)                                                  \
    asm volatile("st.shared.v2.b32 [%0], {%1,%2};" ::"r"(addr), "r"(v0),     \
                 "r"(v1) : "memory")

#define STS128V(addr, v0, v1, v2, v3)                                        \
    asm volatile("st.shared.v4.b32 [%0], {%1,%2,%3,%4};" ::"r"(addr),        \
                 "r"(v0), "r"(v1), "r"(v2), "r"(v3) : "memory")

#define LDSM4(r0, r1, r2, r3, addr)                                          \
    asm volatile("ldmatrix.sync.aligned.m8n8.x4.shared.b16 "                 \
                 "{%0,%1,%2,%3}, [%4];"                                      \
                 : "=r"(r0), "=r"(r1), "=r"(r2), "=r"(r3) : "r"(addr))

#define MMA16816(d, a, b0, b1)                                               \
    asm volatile("mma.sync.aligned.m16n8k16.row.col.f32.bf16.bf16.f32 "      \
                 "{%0,%1,%2,%3}, {%4,%5,%6,%7}, {%8,%9}, {%0,%1,%2,%3};"     \
                 : "+f"((d)[0]), "+f"((d)[1]), "+f"((d)[2]), "+f"((d)[3])    \
                 : "r"((a)[0]), "r"((a)[1]), "r"((a)[2]), "r"((a)[3]),       \
                   "r"(b0), "r"(b1))

#define STG_CS_64(ptr, a, b)                                                 \
    asm volatile("st.global.cs.v2.f32 [%0], {%1,%2};" ::"l"(ptr), "f"(a),    \
                 "f"(b) : "memory")

// swizzled byte offset inside a 256B-pitch bf16 tile (chunk = 16B unit)
__device__ __forceinline__ unsigned sw_off(int row, int chunk) {
    return (unsigned)(row * 256 + ((chunk ^ (row & 7)) << 4));
}

// ============================================================================
// Kernel 0: W[k][n] fp32 -> pre-swizzled bf16 hi/lo tile image in gmem.
// Work item = (nrow, chunk): 8 consecutive k-values of column nrow.
// 2048 work items total (128 rows x 16 chunks) = 32KB per tile.
// ============================================================================
__global__ void wconv_kernel(const float* __restrict__ W) {
    const int idx = blockIdx.x * blockDim.x + threadIdx.x;
    if (idx >= 2048) return;
    const int nrow = idx >> 4;
    const int c    = idx & 15;
    unsigned hi[4], lo[4];
#pragma unroll
    for (int p = 0; p < 4; p++) {
        const int k = c * 8 + p * 2;
        const float wa = W[(size_t)k * D + nrow];
        const float wb = W[(size_t)(k + 1) * D + nrow];
        split2(wa, wb, hi[p], lo[p]);
    }
    const unsigned so = sw_off(nrow, c) >> 4;
    g_BHi4[so] = make_uint4(hi[0], hi[1], hi[2], hi[3]);
    g_BLo4[so] = make_uint4(lo[0], lo[1], lo[2], lo[3]);
}

// ============================================================================
// Fused GINConv: per block of 64 destination rows, 512 threads (16 warps).
//  Phase 0: copy pre-swizzled B tile images (2x32KB) gmem -> smem.
//  Phase 1: gather 4 rows/warp (scalar colidx, f32x2 accumulate) -> smem A.
//  Phase 2: HMMA, warp tile 16x32: D = Ahi*Bhi + Ahi*Blo + Alo*Bhi.
// ============================================================================
__global__ void __launch_bounds__(NT, 2)
ginconv_fused(const float4* __restrict__ X4,
              const int* __restrict__ rowptr,
              const int* __restrict__ colidx,
              float* __restrict__ out,
              int n) {
    extern __shared__ char smem[];
    const unsigned sb = smem_u32(smem);
    const int tid  = threadIdx.x;
    const int wid  = tid >> 5;
    const int lane = tid & 31;
    const int row0 = blockIdx.x * BM;

    // ---- Phase 0: straight copy of pre-swizzled B tiles (32KB each) ----
#pragma unroll
    for (int i = tid; i < 2048; i += NT) {
        const uint4 vh = g_BHi4[i];
        const uint4 vl = g_BLo4[i];
        STS128V(sb + OFF_BHI + i * 16, vh.x, vh.y, vh.z, vh.w);
        STS128V(sb + OFF_BLO + i * 16, vl.x, vl.y, vl.z, vl.w);
    }

    // ---- Phase 1: gather 4 rows per warp into smem A tiles ----
#pragma unroll 1
    for (int t = 0; t < 4; t++) {
        const int lr = wid * 4 + t;
        const int r  = row0 + lr;
        ull_t acc01 = 0ULL, acc23 = 0ULL;  // packed f32x2 accumulators
        if (r < n) {
            int e        = rowptr[r];
            const int e1 = rowptr[r + 1];
            for (; e + 8 <= e1; e += 8) {
                ulonglong2 v[8];
#pragma unroll
                for (int i = 0; i < 8; i++)
                    v[i] = *reinterpret_cast<const ulonglong2*>(
                        X4 + (size_t)colidx[e + i] * 32 + lane);
#pragma unroll
                for (int i = 0; i < 8; i++) {
                    ADD2(acc01, v[i].x);
                    ADD2(acc23, v[i].y);
                }
            }
            for (; e < e1; e++) {
                ulonglong2 v = *reinterpret_cast<const ulonglong2*>(
                    X4 + (size_t)colidx[e] * 32 + lane);
                ADD2(acc01, v.x);
                ADD2(acc23, v.y);
            }
        }
        float ax, ay, az, aw;
        unpack2(acc01, ax, ay);
        unpack2(acc23, az, aw);
        unsigned h0, l0, h1, l1;
        split2(ax, ay, h0, l0);
        split2(az, aw, h1, l1);
        // lane owns features 4*lane..4*lane+3 -> 8B at chunk lane>>1
        const unsigned so = (unsigned)(lr * 256) +
                            ((unsigned)(((lane >> 1) ^ (lr & 7)) << 4)) +
                            (unsigned)((lane & 1) * 8);
        STS64(sb + OFF_AHI + so, h0, h1);
        STS64(sb + OFF_ALO + so, l0, l1);
    }
    __syncthreads();

    // ---- Phase 2: HMMA. 16 warps, warp tile 16 rows x 32 cols ----
    const int wm = wid >> 2;  // 0..3 : rows wm*16 .. +15
    const int wn = wid & 3;   // 0..3 : cols wn*32 .. +31

    float acc[4][4];
#pragma unroll
    for (int nt = 0; nt < 4; nt++)
#pragma unroll
        for (int i = 0; i < 4; i++) acc[nt][i] = 0.f;

    const int lrow = lane & 15;
    const int lch  = lane >> 4;

#pragma unroll 2
    for (int ks = 0; ks < 8; ks++) {
        const int cb = ks * 2 + lch;

        unsigned ah[4], al[4];
        {
            const unsigned so = sw_off(wm * 16 + lrow, cb);
            LDSM4(ah[0], ah[1], ah[2], ah[3], sb + OFF_AHI + so);
            LDSM4(al[0], al[1], al[2], al[3], sb + OFF_ALO + so);
        }
#pragma unroll
        for (int np = 0; np < 2; np++) {
            unsigned bh[4], bl[4];
            const unsigned so = sw_off(wn * 32 + np * 16 + lrow, cb);
            LDSM4(bh[0], bh[1], bh[2], bh[3], sb + OFF_BHI + so);
            LDSM4(bl[0], bl[1], bl[2], bl[3], sb + OFF_BLO + so);
#pragma unroll
            for (int hf = 0; hf < 2; hf++) {
                const int nt = np * 2 + hf;
                MMA16816(acc[nt], ah, bh[hf], bh[hf + 2]);
                MMA16816(acc[nt], ah, bl[hf], bl[hf + 2]);
                MMA16816(acc[nt], al, bh[hf], bh[hf + 2]);
            }
        }
    }

    // ---- Epilogue ----
    {
        const int rg = row0 + wm * 16 + (lane >> 2);
#pragma unroll
        for (int nt = 0; nt < 4; nt++) {
            const int col = wn * 32 + nt * 8 + (lane & 3) * 2;
            if (rg < n)
                STG_CS_64(&out[(size_t)rg * D + col], acc[nt][0], acc[nt][1]);
            if (rg + 8 < n)
                STG_CS_64(&out[(size_t)(rg + 8) * D + col], acc[nt][2],
                          acc[nt][3]);
        }
    }
}

extern "C" void kernel_launch(void* const* d_in, const int* in_sizes, int n_in,
                              void* d_out, int out_size) {
    const float* X      = (const float*)d_in[0];
    const float* W      = (const float*)d_in[1];
    const int*   rowptr = (const int*)d_in[2];
    const int*   colidx = (const int*)d_in[3];
    float*       out    = (float*)d_out;

    const int n = in_sizes[2] - 1;  // row_pointers has N+1 entries

    wconv_kernel<<<8, 256>>>(W);

    cudaFuncSetAttribute(ginconv_fused,
                         cudaFuncAttributeMaxDynamicSharedMemorySize,
                         FUSE_SMEM);

    const int grid = (n + BM - 1) / BM;
    ginconv_fused<<<grid, NT, FUSE_SMEM>>>((const float4*)X, rowptr, colidx,
                                           out, n);
}

// round 16
// speedup vs baseline: 1.5716x; 1.0729x over previous
#include <cuda_runtime.h>
#include <cuda_bf16.h>
#include <cstdint>

#define D 128
#define BM 64
#define NT 512

// smem layout (bytes): A hi 16K | A lo 16K
#define OFF_AHI 0
#define OFF_ALO 16384
#define FUSE_SMEM 32768

// B in mma-fragment order: index = ((ks*4 + wn)*2 + q)*32 + lane.
// uint4 = { tile(2q) reg0, tile(2q) reg1, tile(2q+1) reg0, tile(2q+1) reg1 }
// where tile = n8 group within the warp's 32 cols, reg0 = k0..7, reg1 = k8..15,
// and within a reg: thread holds B[n = lane>>2][k = (lane&3)*2 + {0,1}].
__device__ uint4 g_BfragHi[2048];
__device__ uint4 g_BfragLo[2048];

typedef unsigned long long ull_t;

// ---- helpers ----
__device__ __forceinline__ void split2(float a, float b, unsigned& hi, unsigned& lo) {
    __nv_bfloat16 ha = __float2bfloat16_rn(a);
    __nv_bfloat16 hb = __float2bfloat16_rn(b);
    float ra = a - __bfloat162float(ha);
    float rb = b - __bfloat162float(hb);
    __nv_bfloat162 hv; hv.x = ha; hv.y = hb;
    __nv_bfloat162 lv = __floats2bfloat162_rn(ra, rb);
    hi = *reinterpret_cast<unsigned*>(&hv);
    lo = *reinterpret_cast<unsigned*>(&lv);
}

__device__ __forceinline__ void unpack2(ull_t v, float& lo, float& hi) {
    asm("mov.b64 {%0,%1}, %2;" : "=f"(lo), "=f"(hi) : "l"(v));
}

#define ADD2(d, s)                                                           \
    asm("add.rn.f32x2 %0, %0, %1;" : "+l"(d) : "l"(s))

__device__ __forceinline__ unsigned smem_u32(const void* p) {
    unsigned a;
    asm("{ .reg .u64 t; cvta.to.shared.u64 t, %1; cvt.u32.u64 %0, t; }"
        : "=r"(a) : "l"(p));
    return a;
}

#define STS64(addr, v0, v1)                                                  \
    asm volatile("st.shared.v2.b32 [%0], {%1,%2};" ::"r"(addr), "r"(v0),     \
                 "r"(v1) : "memory")

#define LDSM4(r0, r1, r2, r3, addr)                                          \
    asm volatile("ldmatrix.sync.aligned.m8n8.x4.shared.b16 "                 \
                 "{%0,%1,%2,%3}, [%4];"                                      \
                 : "=r"(r0), "=r"(r1), "=r"(r2), "=r"(r3) : "r"(addr))

#define MMA16816(d, a, b0, b1)                                               \
    asm volatile("mma.sync.aligned.m16n8k16.row.col.f32.bf16.bf16.f32 "      \
                 "{%0,%1,%2,%3}, {%4,%5,%6,%7}, {%8,%9}, {%0,%1,%2,%3};"     \
                 : "+f"((d)[0]), "+f"((d)[1]), "+f"((d)[2]), "+f"((d)[3])    \
                 : "r"((a)[0]), "r"((a)[1]), "r"((a)[2]), "r"((a)[3]),       \
                   "r"(b0), "r"(b1))

#define STG_CS_64(ptr, a, b)                                                 \
    asm volatile("st.global.cs.v2.f32 [%0], {%1,%2};" ::"l"(ptr), "f"(a),    \
                 "f"(b) : "memory")

// swizzled byte offset inside a 256B-pitch bf16 tile (chunk = 16B unit)
__device__ __forceinline__ unsigned sw_off(int row, int chunk) {
    return (unsigned)(row * 256 + ((chunk ^ (row & 7)) << 4));
}

// ============================================================================
// Kernel 0: W[k][n] fp32 -> B fragments (bf16 hi/lo) in mma order.
// 2048 threads; thread -> (ks, wn, q, lane) = idx decomposition.
// ============================================================================
__global__ void wconv_kernel(const float* __restrict__ W) {
    const int idx = blockIdx.x * blockDim.x + threadIdx.x;
    if (idx >= 2048) return;
    const int lane = idx & 31;
    const int q    = (idx >> 5) & 1;
    const int wn   = (idx >> 6) & 3;
    const int ks   = idx >> 8;

    unsigned hi[4], lo[4];
#pragma unroll
    for (int t01 = 0; t01 < 2; t01++) {
        const int tile = 2 * q + t01;
        const int col  = wn * 32 + tile * 8 + (lane >> 2);
#pragma unroll
        for (int r = 0; r < 2; r++) {
            const int k0 = ks * 16 + r * 8 + (lane & 3) * 2;
            const float wa = W[(size_t)k0 * D + col];
            const float wb = W[(size_t)(k0 + 1) * D + col];
            split2(wa, wb, hi[t01 * 2 + r], lo[t01 * 2 + r]);
        }
    }
    g_BfragHi[idx] = make_uint4(hi[0], hi[1], hi[2], hi[3]);
    g_BfragLo[idx] = make_uint4(lo[0], lo[1], lo[2], lo[3]);
}

// ============================================================================
// Fused GINConv: per block of 64 destination rows, 512 threads (16 warps).
//  Phase 1: gather 4 rows/warp (scalar colidx, f32x2 accumulate) -> smem A.
//  Phase 2: HMMA, warp tile 16x32; A via ldmatrix, B fragments straight
//           from L1-resident gmem (no smem B tile, no copy phase).
//  D = Ahi*Bhi + Ahi*Blo + Alo*Bhi (fp32 accumulate).
// ============================================================================
__global__ void __launch_bounds__(NT, 2)
ginconv_fused(const float4* __restrict__ X4,
              const int* __restrict__ rowptr,
              const int* __restrict__ colidx,
              float* __restrict__ out,
              int n) {
    extern __shared__ char smem[];
    const unsigned sb = smem_u32(smem);
    const int tid  = threadIdx.x;
    const int wid  = tid >> 5;
    const int lane = tid & 31;
    const int row0 = blockIdx.x * BM;

    // ---- Phase 1: gather 4 rows per warp into smem A tiles ----
#pragma unroll 1
    for (int t = 0; t < 4; t++) {
        const int lr = wid * 4 + t;
        const int r  = row0 + lr;
        ull_t acc01 = 0ULL, acc23 = 0ULL;  // packed f32x2 accumulators
        if (r < n) {
            int e        = rowptr[r];
            const int e1 = rowptr[r + 1];
            for (; e + 8 <= e1; e += 8) {
                ulonglong2 v[8];
#pragma unroll
                for (int i = 0; i < 8; i++)
                    v[i] = *reinterpret_cast<const ulonglong2*>(
                        X4 + (size_t)colidx[e + i] * 32 + lane);
#pragma unroll
                for (int i = 0; i < 8; i++) {
                    ADD2(acc01, v[i].x);
                    ADD2(acc23, v[i].y);
                }
            }
            for (; e < e1; e++) {
                ulonglong2 v = *reinterpret_cast<const ulonglong2*>(
                    X4 + (size_t)colidx[e] * 32 + lane);
                ADD2(acc01, v.x);
                ADD2(acc23, v.y);
            }
        }
        float ax, ay, az, aw;
        unpack2(acc01, ax, ay);
        unpack2(acc23, az, aw);
        unsigned h0, l0, h1, l1;
        split2(ax, ay, h0, l0);
        split2(az, aw, h1, l1);
        // lane owns features 4*lane..4*lane+3 -> 8B at chunk lane>>1
        const unsigned so = (unsigned)(lr * 256) +
                            ((unsigned)(((lane >> 1) ^ (lr & 7)) << 4)) +
                            (unsigned)((lane & 1) * 8);
        STS64(sb + OFF_AHI + so, h0, h1);
        STS64(sb + OFF_ALO + so, l0, l1);
    }
    __syncthreads();

    // ---- Phase 2: HMMA. 16 warps, warp tile 16 rows x 32 cols ----
    const int wm = wid >> 2;  // 0..3 : rows wm*16 .. +15
    const int wn = wid & 3;   // 0..3 : cols wn*32 .. +31

    float acc[4][4];
#pragma unroll
    for (int nt = 0; nt < 4; nt++)
#pragma unroll
        for (int i = 0; i < 4; i++) acc[nt][i] = 0.f;

    const int lrow = lane & 15;
    const int lch  = lane >> 4;

#pragma unroll 2
    for (int ks = 0; ks < 8; ks++) {
        const int cb = ks * 2 + lch;

        unsigned ah[4], al[4];
        {
            const unsigned so = sw_off(wm * 16 + lrow, cb);
            LDSM4(ah[0], ah[1], ah[2], ah[3], sb + OFF_AHI + so);
            LDSM4(al[0], al[1], al[2], al[3], sb + OFF_ALO + so);
        }

        // B fragments straight from gmem (L1-hot, coalesced LDG.128)
        const int bbase = ((ks * 4 + wn) * 2) * 32 + lane;
        const uint4 H0 = __ldg(&g_BfragHi[bbase]);
        const uint4 H1 = __ldg(&g_BfragHi[bbase + 32]);
        const uint4 L0 = __ldg(&g_BfragLo[bbase]);
        const uint4 L1 = __ldg(&g_BfragLo[bbase + 32]);

        MMA16816(acc[0], ah, H0.x, H0.y);
        MMA16816(acc[0], ah, L0.x, L0.y);
        MMA16816(acc[0], al, H0.x, H0.y);

        MMA16816(acc[1], ah, H0.z, H0.w);
        MMA16816(acc[1], ah, L0.z, L0.w);
        MMA16816(acc[1], al, H0.z, H0.w);

        MMA16816(acc[2], ah, H1.x, H1.y);
        MMA16816(acc[2], ah, L1.x, L1.y);
        MMA16816(acc[2], al, H1.x, H1.y);

        MMA16816(acc[3], ah, H1.z, H1.w);
        MMA16816(acc[3], ah, L1.z, L1.w);
        MMA16816(acc[3], al, H1.z, H1.w);
    }

    // ---- Epilogue ----
    {
        const int rg = row0 + wm * 16 + (lane >> 2);
#pragma unroll
        for (int nt = 0; nt < 4; nt++) {
            const int col = wn * 32 + nt * 8 + (lane & 3) * 2;
            if (rg < n)
                STG_CS_64(&out[(size_t)rg * D + col], acc[nt][0], acc[nt][1]);
            if (rg + 8 < n)
                STG_CS_64(&out[(size_t)(rg + 8) * D + col], acc[nt][2],
                          acc[nt][3]);
        }
    }
}

extern "C" void kernel_launch(void* const* d_in, const int* in_sizes, int n_in,
                              void* d_out, int out_size) {
    const float* X      = (const float*)d_in[0];
    const float* W      = (const float*)d_in[1];
    const int*   rowptr = (const int*)d_in[2];
    const int*   colidx = (const int*)d_in[3];
    float*       out    = (float*)d_out;

    const int n = in_sizes[2] - 1;  // row_pointers has N+1 entries

    wconv_kernel<<<8, 256>>>(W);

    cudaFuncSetAttribute(ginconv_fused,
                         cudaFuncAttributeMaxDynamicSharedMemorySize,
                         FUSE_SMEM);

    const int grid = (n + BM - 1) / BM;
    ginconv_fused<<<grid, NT, FUSE_SMEM>>>((const float4*)X, rowptr, colidx,
                                           out, n);
}